// round 11
// baseline (speedup 1.0000x reference)
#include <cuda_runtime.h>
#include <cuda_bf16.h>
#include <math.h>
#include <stdint.h>

#define BB 2
#define TT 2048
#define DDIM 2048
#define HH 16
#define HDIM 128
#define MR (BB * TT)        // 4096
#define NQKV (3 * DDIM)     // 6144

// ---------------- scratch (device globals: allocation-free) ----------------
__device__ float g_qkv[(size_t)MR * NQKV];     // [B*T, 3D] fp32
__device__ float g_y[(size_t)MR * DDIM];       // [B*T, D] fp32
__device__ __nv_bfloat16 g_xh[(size_t)MR * DDIM],   g_xl[(size_t)MR * DDIM];
__device__ __nv_bfloat16 g_wah[(size_t)NQKV * DDIM], g_wal[(size_t)NQKV * DDIM]; // [N,K]
__device__ __nv_bfloat16 g_wph[(size_t)DDIM * DDIM], g_wpl[(size_t)DDIM * DDIM]; // [N,K]
__device__ __nv_bfloat16 g_yh[(size_t)MR * DDIM],   g_yl[(size_t)MR * DDIM];

// ---------------- helpers ----------------
__device__ __forceinline__ uint32_t smem_u32(const void* p) {
    uint32_t a;
    asm("{ .reg .u64 t; cvta.to.shared.u64 t, %1; cvt.u32.u64 %0, t; }" : "=r"(a) : "l"(p));
    return a;
}
__device__ __forceinline__ void cp16(uint32_t dst, const void* src) {
    asm volatile("cp.async.cg.shared.global [%0], [%1], 16;\n" :: "r"(dst), "l"(src) : "memory");
}
__device__ __forceinline__ void cp_commit() { asm volatile("cp.async.commit_group;\n" ::: "memory"); }
__device__ __forceinline__ void cp_wait1()  { asm volatile("cp.async.wait_group 1;\n" ::: "memory"); }
__device__ __forceinline__ void cp_wait0()  { asm volatile("cp.async.wait_group 0;\n" ::: "memory"); }

__device__ __forceinline__ void ldsm4(uint32_t* r, uint32_t addr) {
    asm volatile("ldmatrix.sync.aligned.m8n8.x4.shared.b16 {%0,%1,%2,%3}, [%4];"
                 : "=r"(r[0]), "=r"(r[1]), "=r"(r[2]), "=r"(r[3]) : "r"(addr));
}
__device__ __forceinline__ void mma16816(float* c, const uint32_t* a, const uint32_t* b) {
    asm volatile(
        "mma.sync.aligned.m16n8k16.row.col.f32.bf16.bf16.f32 "
        "{%0,%1,%2,%3}, {%4,%5,%6,%7}, {%8,%9}, {%0,%1,%2,%3};"
        : "+f"(c[0]), "+f"(c[1]), "+f"(c[2]), "+f"(c[3])
        : "r"(a[0]), "r"(a[1]), "r"(a[2]), "r"(a[3]), "r"(b[0]), "r"(b[1]));
}
// FMA-pipe exp (no MUFU). x <= 0 expected; clamped at -80. rel err ~2e-7.
__device__ __forceinline__ float fast_exp(float x) {
    x = fmaxf(x, -80.f);
    float y = x * 1.4426950408889634f;
    float t = y + 12582912.f;                       // round-to-nearest via 1.5*2^23
    int   r = __float_as_int(t) - 0x4B400000;
    float f = y - (t - 12582912.f);                 // f in [-0.5, 0.5]
    float p =            1.8775767e-3f;
    p = fmaf(p, f, 8.9893397e-3f);
    p = fmaf(p, f, 5.5826318e-2f);
    p = fmaf(p, f, 2.4015361e-1f);
    p = fmaf(p, f, 6.9315308e-1f);
    p = fmaf(p, f, 1.0f);
    return __int_as_float(__float_as_int(p) + (r << 23));
}

// ---------------- bf16 split conversion kernels ----------------
__device__ __forceinline__ uint32_t pack2(__nv_bfloat16 a, __nv_bfloat16 b) {
    __nv_bfloat162 t; t.x = a; t.y = b;
    return *(uint32_t*)&t;
}

__device__ __forceinline__ void split_body(const float* __restrict__ src,
                                           __nv_bfloat16* __restrict__ hi,
                                           __nv_bfloat16* __restrict__ lo) {
    size_t i = (size_t)blockIdx.x * blockDim.x + threadIdx.x;  // one float4
    float4 v = ((const float4*)src)[i];
    float f[4] = {v.x, v.y, v.z, v.w};
    __nv_bfloat16 h[4], l[4];
#pragma unroll
    for (int j = 0; j < 4; j++) {
        h[j] = __float2bfloat16(f[j]);
        l[j] = __float2bfloat16(f[j] - __bfloat162float(h[j]));
    }
    ((uint2*)hi)[i] = make_uint2(pack2(h[0], h[1]), pack2(h[2], h[3]));
    ((uint2*)lo)[i] = make_uint2(pack2(l[0], l[1]), pack2(l[2], l[3]));
}

__global__ void __launch_bounds__(256) split_x_kernel(const float* __restrict__ x) {
    split_body(x, g_xh, g_xl);
}
__global__ void __launch_bounds__(256) split_y_kernel() {
    split_body(g_y, g_yh, g_yl);
}

// src [K,N] row-major fp32 -> hi/lo [N,K] bf16 (transposed split)
__device__ __forceinline__ void splitT_body(const float* __restrict__ src,
                                            __nv_bfloat16* __restrict__ hi,
                                            __nv_bfloat16* __restrict__ lo,
                                            int K, int N) {
    __shared__ float t[32][33];
    int tx = threadIdx.x, ty = threadIdx.y;
    int n0 = blockIdx.x * 32, k0 = blockIdx.y * 32;
#pragma unroll
    for (int i = 0; i < 4; i++)
        t[ty + i * 8][tx] = src[(size_t)(k0 + ty + i * 8) * N + n0 + tx];
    __syncthreads();
#pragma unroll
    for (int i = 0; i < 4; i++) {
        float v = t[tx][ty + i * 8];
        __nv_bfloat16 h = __float2bfloat16(v);
        __nv_bfloat16 l = __float2bfloat16(v - __bfloat162float(h));
        size_t o = (size_t)(n0 + ty + i * 8) * K + k0 + tx;
        hi[o] = h; lo[o] = l;
    }
}

__global__ void split_wa_kernel(const float* __restrict__ w) { splitT_body(w, g_wah, g_wal, DDIM, NQKV); }
__global__ void split_wp_kernel(const float* __restrict__ w) { splitT_body(w, g_wph, g_wpl, DDIM, DDIM); }

// ---------------- mma.sync bf16-split GEMM (round-8 proven core, verbatim) ----------------
#define TSZ 8192
#define STAGE_SZ (4 * TSZ)
#define SMEM_MMA (2 * STAGE_SZ)

__device__ __forceinline__ uint32_t tile_off(int r, int cbyte) {
    return (uint32_t)(r * 64 + ((((cbyte >> 4) ^ ((r >> 1) & 3)) << 4)));
}

__device__ __forceinline__ void load_stage_mma(uint32_t base,
    const __nv_bfloat16* __restrict__ Ah, const __nv_bfloat16* __restrict__ Al,
    const __nv_bfloat16* __restrict__ Bh, const __nv_bfloat16* __restrict__ Bl,
    int m0, int n0, int k0, int K, int tid)
{
#pragma unroll
    for (int half = 0; half < 2; half++) {
        int idx = half * 256 + tid;
        int r = idx >> 2, c = (idx & 3);
        uint32_t o = tile_off(r, c * 16);
        const size_t ao = (size_t)(m0 + r) * K + k0 + c * 8;
        const size_t bo = (size_t)(n0 + r) * K + k0 + c * 8;
        cp16(base + o,           Ah + ao);
        cp16(base + TSZ + o,     Al + ao);
        cp16(base + 2 * TSZ + o, Bh + bo);
        cp16(base + 3 * TSZ + o, Bl + bo);
    }
}

__device__ void gemm_mma_body(const __nv_bfloat16* __restrict__ Ah, const __nv_bfloat16* __restrict__ Al,
                              const __nv_bfloat16* __restrict__ Bh, const __nv_bfloat16* __restrict__ Bl,
                              float* __restrict__ C, int M, int N, int K)
{
    extern __shared__ char smem[];
    const uint32_t sb = smem_u32(smem);
    const int tid  = threadIdx.x;
    const int lane = tid & 31;
    const int wid  = tid >> 5;
    const int wm   = wid & 3;
    const int wn   = wid >> 2;
    const int m0 = blockIdx.y * 128;
    const int n0 = blockIdx.x * 128;

    float acc[2][8][4];
#pragma unroll
    for (int i = 0; i < 2; i++)
#pragma unroll
        for (int j = 0; j < 8; j++)
#pragma unroll
            for (int q = 0; q < 4; q++) acc[i][j][q] = 0.f;

    const int a_r  = (lane & 7) + ((lane >> 3) & 1) * 8;
    const int a_kb = (lane >> 4) * 16;
    const int b_r  = (lane & 7) + ((lane >> 4) << 3);
    const int b_kb = ((lane >> 3) & 1) * 16;

    const int NIT = K / 32;
    load_stage_mma(sb,            Ah, Al, Bh, Bl, m0, n0, 0,  K, tid); cp_commit();
    load_stage_mma(sb + STAGE_SZ, Ah, Al, Bh, Bl, m0, n0, 32, K, tid); cp_commit();

    for (int it = 0; it < NIT; ++it) {
        if (it + 1 < NIT) cp_wait1(); else cp_wait0();
        __syncthreads();
        const uint32_t st = sb + (uint32_t)(it & 1) * STAGE_SZ;
#pragma unroll
        for (int k16 = 0; k16 < 2; k16++) {
#pragma unroll
            for (int p = 0; p < 3; p++) {
                const uint32_t at = st + ((p == 2) ? TSZ : 0);
                const uint32_t bt = st + 2 * TSZ + ((p == 1) ? TSZ : 0);
                uint32_t a[2][4];
#pragma unroll
                for (int mf = 0; mf < 2; mf++) {
                    int r = wm * 32 + mf * 16 + a_r;
                    ldsm4(a[mf], at + tile_off(r, k16 * 32 + a_kb));
                }
                uint32_t b[8][2];
#pragma unroll
                for (int g = 0; g < 4; g++) {
                    int r = wn * 64 + g * 16 + b_r;
                    uint32_t t[4];
                    ldsm4(t, bt + tile_off(r, k16 * 32 + b_kb));
                    b[2 * g][0] = t[0]; b[2 * g][1] = t[1];
                    b[2 * g + 1][0] = t[2]; b[2 * g + 1][1] = t[3];
                }
#pragma unroll
                for (int mf = 0; mf < 2; mf++)
#pragma unroll
                    for (int nf = 0; nf < 8; nf++)
                        mma16816(acc[mf][nf], a[mf], b[nf]);
            }
        }
        __syncthreads();
        if (it + 2 < NIT) {
            load_stage_mma(st, Ah, Al, Bh, Bl, m0, n0, (it + 2) * 32, K, tid);
            cp_commit();
        }
    }

    const int rr = lane >> 2;
    const int cc = (lane & 3) * 2;
#pragma unroll
    for (int mf = 0; mf < 2; mf++) {
        const int row = m0 + wm * 32 + mf * 16 + rr;
#pragma unroll
        for (int nf = 0; nf < 8; nf++) {
            const int col = n0 + wn * 64 + nf * 8 + cc;
            *(float2*)(C + (size_t)row * N + col)       = make_float2(acc[mf][nf][0], acc[mf][nf][1]);
            *(float2*)(C + (size_t)(row + 8) * N + col) = make_float2(acc[mf][nf][2], acc[mf][nf][3]);
        }
    }
}

__global__ void __launch_bounds__(256, 2) qkv_gemm_kernel() {
    gemm_mma_body(g_xh, g_xl, g_wah, g_wal, g_qkv, MR, NQKV, DDIM);
}
__global__ void __launch_bounds__(256, 2) proj_gemm_kernel(float* __restrict__ out) {
    gemm_mma_body(g_yh, g_yl, g_wph, g_wpl, out, MR, DDIM, DDIM);
}

// ---------------------------------------------------------------------------
// Flash attention (causal, fp32) — round-8 proven kernel, __expf -> fast_exp.
// ---------------------------------------------------------------------------
#define LQ 132
#define LK 68
#define LP 65
#define SMEM_FLASH ((64 * LQ + 128 * LK + 64 * LQ + 64 * LP) * sizeof(float))

__global__ void __launch_bounds__(256) flash_kernel()
{
    extern __shared__ float sm[];
    float* Qs  = sm;
    float* Kts = Qs + 64 * LQ;
    float* Vs  = Kts + 128 * LK;
    float* Ps  = Vs + 64 * LQ;

    const int qt = blockIdx.x;
    const int h  = blockIdx.y;
    const int b  = blockIdx.z;
    const int tid = threadIdx.x;
    const int ty = tid >> 4;
    const int tx = tid & 15;

    const int q0 = qt * 64;
    const float* base = g_qkv + (size_t)b * TT * NQKV + h * HDIM;

    {
        int r  = tid >> 2;
        int c0 = (tid & 3) * 32;
        const float* src = base + (size_t)(q0 + r) * NQKV + c0;
        float* dst = Qs + r * LQ + c0;
#pragma unroll
        for (int i = 0; i < 8; i++) ((float4*)dst)[i] = ((const float4*)src)[i];
    }

    float o[4][8];
#pragma unroll
    for (int i = 0; i < 4; i++)
#pragma unroll
        for (int c = 0; c < 8; c++) o[i][c] = 0.f;

    float m_i[4], l_i[4];
#pragma unroll
    for (int i = 0; i < 4; i++) { m_i[i] = -INFINITY; l_i[i] = 0.f; }

    const float scale = 0.088388347648318447f;

    for (int kt = 0; kt <= qt; kt++) {
        const int k0 = kt * 64;
        __syncthreads();
        {
            int r  = tid >> 2;
            int c0 = (tid & 3) * 32;
            const float* ks = base + (size_t)(k0 + r) * NQKV + DDIM + c0;
#pragma unroll
            for (int i = 0; i < 8; i++) {
                float4 v = ((const float4*)ks)[i];
                int c = c0 + i * 4;
                Kts[(c + 0) * LK + r] = v.x;
                Kts[(c + 1) * LK + r] = v.y;
                Kts[(c + 2) * LK + r] = v.z;
                Kts[(c + 3) * LK + r] = v.w;
            }
            const float* vs = base + (size_t)(k0 + r) * NQKV + 2 * DDIM + c0;
            float* vd = Vs + r * LQ + c0;
#pragma unroll
            for (int i = 0; i < 8; i++) ((float4*)vd)[i] = ((const float4*)vs)[i];
        }
        __syncthreads();

        float s[4][4];
#pragma unroll
        for (int i = 0; i < 4; i++)
#pragma unroll
            for (int j = 0; j < 4; j++) s[i][j] = 0.f;

#pragma unroll 8
        for (int d0 = 0; d0 < HDIM; d0 += 4) {
            float4 q[4];
#pragma unroll
            for (int i = 0; i < 4; i++)
                q[i] = *(const float4*)(Qs + (4 * ty + i) * LQ + d0);
#pragma unroll
            for (int dd = 0; dd < 4; dd++) {
                float4 kv = *(const float4*)(Kts + (d0 + dd) * LK + 4 * tx);
#pragma unroll
                for (int i = 0; i < 4; i++) {
                    float qd = ((const float*)&q[i])[dd];
                    s[i][0] = fmaf(qd, kv.x, s[i][0]);
                    s[i][1] = fmaf(qd, kv.y, s[i][1]);
                    s[i][2] = fmaf(qd, kv.z, s[i][2]);
                    s[i][3] = fmaf(qd, kv.w, s[i][3]);
                }
            }
        }

        const bool diag = (kt == qt);
#pragma unroll
        for (int i = 0; i < 4; i++)
#pragma unroll
            for (int j = 0; j < 4; j++) {
                float v = s[i][j] * scale;
                if (diag && (4 * tx + j > 4 * ty + i)) v = -INFINITY;
                s[i][j] = v;
            }

        float rsum[4], alpha[4];
#pragma unroll
        for (int i = 0; i < 4; i++) {
            float v = fmaxf(fmaxf(s[i][0], s[i][1]), fmaxf(s[i][2], s[i][3]));
#pragma unroll
            for (int off = 8; off; off >>= 1)
                v = fmaxf(v, __shfl_xor_sync(0xffffffffu, v, off, 16));
            float mnew = fmaxf(m_i[i], v);
            alpha[i] = fast_exp(m_i[i] - mnew);
            m_i[i] = mnew;
            float rs = 0.f;
#pragma unroll
            for (int j = 0; j < 4; j++) {
                float p = fast_exp(s[i][j] - mnew);
                Ps[(4 * ty + i) * LP + 4 * tx + j] = p;
                rs += p;
            }
#pragma unroll
            for (int off = 8; off; off >>= 1)
                rs += __shfl_xor_sync(0xffffffffu, rs, off, 16);
            rsum[i] = rs;
        }
#pragma unroll
        for (int i = 0; i < 4; i++) {
            l_i[i] = l_i[i] * alpha[i] + rsum[i];
#pragma unroll
            for (int c = 0; c < 8; c++) o[i][c] *= alpha[i];
        }
        __syncthreads();

#pragma unroll 8
        for (int j = 0; j < 64; j++) {
            float4 v0 = *(const float4*)(Vs + j * LQ + 8 * tx);
            float4 v1 = *(const float4*)(Vs + j * LQ + 8 * tx + 4);
#pragma unroll
            for (int i = 0; i < 4; i++) {
                float p = Ps[(4 * ty + i) * LP + j];
                o[i][0] = fmaf(p, v0.x, o[i][0]);
                o[i][1] = fmaf(p, v0.y, o[i][1]);
                o[i][2] = fmaf(p, v0.z, o[i][2]);
                o[i][3] = fmaf(p, v0.w, o[i][3]);
                o[i][4] = fmaf(p, v1.x, o[i][4]);
                o[i][5] = fmaf(p, v1.y, o[i][5]);
                o[i][6] = fmaf(p, v1.z, o[i][6]);
                o[i][7] = fmaf(p, v1.w, o[i][7]);
            }
        }
    }

#pragma unroll
    for (int i = 0; i < 4; i++) {
        float inv = 1.f / l_i[i];
        int row = q0 + 4 * ty + i;
        float* dst = g_y + (size_t)(b * TT + row) * DDIM + h * HDIM + 8 * tx;
        *(float4*)dst       = make_float4(o[i][0] * inv, o[i][1] * inv, o[i][2] * inv, o[i][3] * inv);
        *(float4*)(dst + 4) = make_float4(o[i][4] * inv, o[i][5] * inv, o[i][6] * inv, o[i][7] * inv);
    }
}

// ---------------------------------------------------------------------------
extern "C" void kernel_launch(void* const* d_in, const int* in_sizes, int n_in,
                              void* d_out, int out_size)
{
    (void)in_sizes; (void)n_in; (void)out_size;
    const float* x      = (const float*)d_in[0];
    const float* w_attn = (const float*)d_in[1];
    const float* w_proj = (const float*)d_in[2];
    float* out = (float*)d_out;

    cudaFuncSetAttribute(flash_kernel,     cudaFuncAttributeMaxDynamicSharedMemorySize, (int)SMEM_FLASH);
    cudaFuncSetAttribute(qkv_gemm_kernel,  cudaFuncAttributeMaxDynamicSharedMemorySize, SMEM_MMA);
    cudaFuncSetAttribute(proj_gemm_kernel, cudaFuncAttributeMaxDynamicSharedMemorySize, SMEM_MMA);

    split_x_kernel<<<(size_t)MR * DDIM / 4 / 256, 256>>>(x);
    split_wa_kernel<<<dim3(NQKV / 32, DDIM / 32), dim3(32, 8)>>>(w_attn);
    split_wp_kernel<<<dim3(DDIM / 32, DDIM / 32), dim3(32, 8)>>>(w_proj);

    qkv_gemm_kernel<<<dim3(NQKV / 128, MR / 128), 256, SMEM_MMA>>>();

    flash_kernel<<<dim3(TT / 64, HH, BB), 256, SMEM_FLASH>>>();

    split_y_kernel<<<(size_t)MR * DDIM / 4 / 256, 256>>>();

    proj_gemm_kernel<<<dim3(DDIM / 128, MR / 128), 256, SMEM_MMA>>>(out);
}

// round 14
// speedup vs baseline: 1.7695x; 1.7695x over previous
#include <cuda_runtime.h>
#include <cuda_bf16.h>
#include <math.h>
#include <stdint.h>

#define BB 2
#define TT 2048
#define DDIM 2048
#define HH 16
#define HDIM 128
#define MR (BB * TT)        // 4096
#define NQKV (3 * DDIM)     // 6144

// ---------------- scratch (device globals: allocation-free) ----------------
__device__ float g_qkv[(size_t)MR * NQKV];     // [B*T, 3D] fp32
__device__ float g_y[(size_t)MR * DDIM];       // [B*T, D] fp32
__device__ __nv_bfloat16 g_xh[(size_t)MR * DDIM],    g_xl[(size_t)MR * DDIM];
__device__ __nv_bfloat16 g_wah[(size_t)NQKV * DDIM], g_wal[(size_t)NQKV * DDIM]; // [N,K]
__device__ __nv_bfloat16 g_wph[(size_t)DDIM * DDIM], g_wpl[(size_t)DDIM * DDIM]; // [N,K]
__device__ __nv_bfloat16 g_yh[(size_t)MR * DDIM],    g_yl[(size_t)MR * DDIM];
// Q,K hi/lo: row stride 2*DDIM (cols 0..2D-1 of qkv). Readers MUST use 2*DDIM.
__device__ __nv_bfloat16 g_qkvh[(size_t)MR * 2 * DDIM], g_qkvl[(size_t)MR * 2 * DDIM];
__device__ __nv_bfloat16 g_vth[(size_t)BB * HH * HDIM * TT],  // V^T [b*H+h][d][token]
                         g_vtl[(size_t)BB * HH * HDIM * TT];

// ---------------- helpers ----------------
__device__ __forceinline__ uint32_t smem_u32(const void* p) {
    uint32_t a;
    asm("{ .reg .u64 t; cvta.to.shared.u64 t, %1; cvt.u32.u64 %0, t; }" : "=r"(a) : "l"(p));
    return a;
}
__device__ __forceinline__ void cp16(uint32_t dst, const void* src) {
    asm volatile("cp.async.cg.shared.global [%0], [%1], 16;\n" :: "r"(dst), "l"(src) : "memory");
}
__device__ __forceinline__ void cp_commit() { asm volatile("cp.async.commit_group;\n" ::: "memory"); }
__device__ __forceinline__ void cp_wait1()  { asm volatile("cp.async.wait_group 1;\n" ::: "memory"); }
__device__ __forceinline__ void cp_wait0()  { asm volatile("cp.async.wait_group 0;\n" ::: "memory"); }

__device__ __forceinline__ void ldsm4(uint32_t* r, uint32_t addr) {
    asm volatile("ldmatrix.sync.aligned.m8n8.x4.shared.b16 {%0,%1,%2,%3}, [%4];"
                 : "=r"(r[0]), "=r"(r[1]), "=r"(r[2]), "=r"(r[3]) : "r"(addr));
}
__device__ __forceinline__ void mma16816(float* c, const uint32_t* a, const uint32_t* b) {
    asm volatile(
        "mma.sync.aligned.m16n8k16.row.col.f32.bf16.bf16.f32 "
        "{%0,%1,%2,%3}, {%4,%5,%6,%7}, {%8,%9}, {%0,%1,%2,%3};"
        : "+f"(c[0]), "+f"(c[1]), "+f"(c[2]), "+f"(c[3])
        : "r"(a[0]), "r"(a[1]), "r"(a[2]), "r"(a[3]), "r"(b[0]), "r"(b[1]));
}
__device__ __forceinline__ uint32_t pack2(__nv_bfloat16 a, __nv_bfloat16 b) {
    __nv_bfloat162 t; t.x = a; t.y = b;
    return *(uint32_t*)&t;
}
__device__ __forceinline__ void splitpack(float a, float b, uint32_t& ph, uint32_t& pl) {
    __nv_bfloat16 ha = __float2bfloat16(a);
    __nv_bfloat16 hb = __float2bfloat16(b);
    __nv_bfloat16 la = __float2bfloat16(a - __bfloat162float(ha));
    __nv_bfloat16 lb = __float2bfloat16(b - __bfloat162float(hb));
    ph = pack2(ha, hb); pl = pack2(la, lb);
}
// FMA-pipe exp. x <= 0 expected; clamped at -80. rel err ~2e-7.
__device__ __forceinline__ float fast_exp(float x) {
    x = fmaxf(x, -80.f);
    float y = x * 1.4426950408889634f;
    float t = y + 12582912.f;
    int   r = __float_as_int(t) - 0x4B400000;
    float f = y - (t - 12582912.f);
    float p =            1.8775767e-3f;
    p = fmaf(p, f, 8.9893397e-3f);
    p = fmaf(p, f, 5.5826318e-2f);
    p = fmaf(p, f, 2.4015361e-1f);
    p = fmaf(p, f, 6.9315308e-1f);
    p = fmaf(p, f, 1.0f);
    return __int_as_float(__float_as_int(p) + (r << 23));
}

// ---------------- bf16 split conversion kernels ----------------
__device__ __forceinline__ void split_body(const float* __restrict__ src,
                                           __nv_bfloat16* __restrict__ hi,
                                           __nv_bfloat16* __restrict__ lo) {
    size_t i = (size_t)blockIdx.x * blockDim.x + threadIdx.x;
    float4 v = ((const float4*)src)[i];
    uint32_t h0, l0, h1, l1;
    splitpack(v.x, v.y, h0, l0);
    splitpack(v.z, v.w, h1, l1);
    ((uint2*)hi)[i] = make_uint2(h0, h1);
    ((uint2*)lo)[i] = make_uint2(l0, l1);
}
__global__ void __launch_bounds__(256) split_x_kernel(const float* __restrict__ x) {
    split_body(x, g_xh, g_xl);
}
__global__ void __launch_bounds__(256) split_y_kernel() {
    split_body(g_y, g_yh, g_yl);
}

// src [K,N] fp32 -> hi/lo [N,K] bf16 (transposed split)
__device__ __forceinline__ void splitT_body(const float* __restrict__ src,
                                            __nv_bfloat16* __restrict__ hi,
                                            __nv_bfloat16* __restrict__ lo,
                                            int K, int N) {
    __shared__ float t[32][33];
    int tx = threadIdx.x, ty = threadIdx.y;
    int n0 = blockIdx.x * 32, k0 = blockIdx.y * 32;
#pragma unroll
    for (int i = 0; i < 4; i++)
        t[ty + i * 8][tx] = src[(size_t)(k0 + ty + i * 8) * N + n0 + tx];
    __syncthreads();
#pragma unroll
    for (int i = 0; i < 4; i++) {
        float v = t[tx][ty + i * 8];
        __nv_bfloat16 h = __float2bfloat16(v);
        __nv_bfloat16 l = __float2bfloat16(v - __bfloat162float(h));
        size_t o = (size_t)(n0 + ty + i * 8) * K + k0 + tx;
        hi[o] = h; lo[o] = l;
    }
}
__global__ void split_wa_kernel(const float* __restrict__ w) { splitT_body(w, g_wah, g_wal, DDIM, NQKV); }
__global__ void split_wp_kernel(const float* __restrict__ w) { splitT_body(w, g_wph, g_wpl, DDIM, DDIM); }

// V fp32 [token][d] (inside g_qkv) -> V^T hi/lo bf16 [b*H+h][d][token]
__global__ void vtrans_kernel() {
    __shared__ float t[32][33];
    int txx = threadIdx.x, tyy = threadIdx.y;
    int t0 = blockIdx.x * 32, d0 = blockIdx.y * 32;
    int bh = blockIdx.z; int b = bh >> 4, h = bh & 15;
    const size_t rowbase = (size_t)b * TT;
#pragma unroll
    for (int i = 0; i < 4; i++)
        t[tyy + i * 8][txx] =
            g_qkv[(rowbase + t0 + tyy + i * 8) * NQKV + 2 * DDIM + h * HDIM + d0 + txx];
    __syncthreads();
    const size_t vb = (size_t)bh * HDIM * TT;
#pragma unroll
    for (int i = 0; i < 4; i++) {
        float v = t[txx][tyy + i * 8];
        __nv_bfloat16 hi = __float2bfloat16(v);
        __nv_bfloat16 lo = __float2bfloat16(v - __bfloat162float(hi));
        size_t o = vb + (size_t)(d0 + tyy + i * 8) * TT + t0 + txx;
        g_vth[o] = hi; g_vtl[o] = lo;
    }
}

// ---------------- mma.sync bf16-split GEMM (round-8 proven core) ----------------
#define TSZ 8192
#define STAGE_SZ (4 * TSZ)
#define SMEM_MMA (2 * STAGE_SZ)

__device__ __forceinline__ uint32_t tile_off(int r, int cbyte) {
    return (uint32_t)(r * 64 + ((((cbyte >> 4) ^ ((r >> 1) & 3)) << 4)));
}

__device__ __forceinline__ void load_stage_mma(uint32_t base,
    const __nv_bfloat16* __restrict__ Ah, const __nv_bfloat16* __restrict__ Al,
    const __nv_bfloat16* __restrict__ Bh, const __nv_bfloat16* __restrict__ Bl,
    int m0, int n0, int k0, int K, int tid)
{
#pragma unroll
    for (int half = 0; half < 2; half++) {
        int idx = half * 256 + tid;
        int r = idx >> 2, c = (idx & 3);
        uint32_t o = tile_off(r, c * 16);
        const size_t ao = (size_t)(m0 + r) * K + k0 + c * 8;
        const size_t bo = (size_t)(n0 + r) * K + k0 + c * 8;
        cp16(base + o,           Ah + ao);
        cp16(base + TSZ + o,     Al + ao);
        cp16(base + 2 * TSZ + o, Bh + bo);
        cp16(base + 3 * TSZ + o, Bl + bo);
    }
}

// OUTMODE 0: fp32 C only. OUTMODE 1: fp32 C + hi/lo bf16 (g_qkvh/l, stride 2*DDIM) for cols < 2*DDIM.
template<int OUTMODE>
__device__ void gemm_mma_body(const __nv_bfloat16* __restrict__ Ah, const __nv_bfloat16* __restrict__ Al,
                              const __nv_bfloat16* __restrict__ Bh, const __nv_bfloat16* __restrict__ Bl,
                              float* __restrict__ C, int M, int N, int K)
{
    extern __shared__ char smem[];
    const uint32_t sb = smem_u32(smem);
    const int tid  = threadIdx.x;
    const int lane = tid & 31;
    const int wid  = tid >> 5;
    const int wm   = wid & 3;
    const int wn   = wid >> 2;
    const int m0 = blockIdx.y * 128;
    const int n0 = blockIdx.x * 128;

    float acc[2][8][4];
#pragma unroll
    for (int i = 0; i < 2; i++)
#pragma unroll
        for (int j = 0; j < 8; j++)
#pragma unroll
            for (int q = 0; q < 4; q++) acc[i][j][q] = 0.f;

    const int a_r  = (lane & 7) + ((lane >> 3) & 1) * 8;
    const int a_kb = (lane >> 4) * 16;
    const int b_r  = (lane & 7) + ((lane >> 4) << 3);
    const int b_kb = ((lane >> 3) & 1) * 16;

    const int NIT = K / 32;
    load_stage_mma(sb,            Ah, Al, Bh, Bl, m0, n0, 0,  K, tid); cp_commit();
    load_stage_mma(sb + STAGE_SZ, Ah, Al, Bh, Bl, m0, n0, 32, K, tid); cp_commit();

    for (int it = 0; it < NIT; ++it) {
        if (it + 1 < NIT) cp_wait1(); else cp_wait0();
        __syncthreads();
        const uint32_t st = sb + (uint32_t)(it & 1) * STAGE_SZ;
#pragma unroll
        for (int k16 = 0; k16 < 2; k16++) {
#pragma unroll
            for (int p = 0; p < 3; p++) {
                const uint32_t at = st + ((p == 2) ? TSZ : 0);
                const uint32_t bt = st + 2 * TSZ + ((p == 1) ? TSZ : 0);
                uint32_t a[2][4];
#pragma unroll
                for (int mf = 0; mf < 2; mf++) {
                    int r = wm * 32 + mf * 16 + a_r;
                    ldsm4(a[mf], at + tile_off(r, k16 * 32 + a_kb));
                }
                uint32_t b[8][2];
#pragma unroll
                for (int g = 0; g < 4; g++) {
                    int r = wn * 64 + g * 16 + b_r;
                    uint32_t t[4];
                    ldsm4(t, bt + tile_off(r, k16 * 32 + b_kb));
                    b[2 * g][0] = t[0]; b[2 * g][1] = t[1];
                    b[2 * g + 1][0] = t[2]; b[2 * g + 1][1] = t[3];
                }
#pragma unroll
                for (int mf = 0; mf < 2; mf++)
#pragma unroll
                    for (int nf = 0; nf < 8; nf++)
                        mma16816(acc[mf][nf], a[mf], b[nf]);
            }
        }
        __syncthreads();
        if (it + 2 < NIT) {
            load_stage_mma(st, Ah, Al, Bh, Bl, m0, n0, (it + 2) * 32, K, tid);
            cp_commit();
        }
    }

    const int rr = lane >> 2;
    const int cc = (lane & 3) * 2;
    const bool wr_hl = (OUTMODE == 1) && (n0 < 2 * DDIM);
#pragma unroll
    for (int mf = 0; mf < 2; mf++) {
        const int row = m0 + wm * 32 + mf * 16 + rr;
#pragma unroll
        for (int nf = 0; nf < 8; nf++) {
            const int col = n0 + wn * 64 + nf * 8 + cc;
            *(float2*)(C + (size_t)row * N + col)       = make_float2(acc[mf][nf][0], acc[mf][nf][1]);
            *(float2*)(C + (size_t)(row + 8) * N + col) = make_float2(acc[mf][nf][2], acc[mf][nf][3]);
            if (wr_hl) {
                uint32_t h0, l0, h1, l1;
                splitpack(acc[mf][nf][0], acc[mf][nf][1], h0, l0);
                splitpack(acc[mf][nf][2], acc[mf][nf][3], h1, l1);
                const size_t o0 = ((size_t)row * (2 * DDIM) + col) >> 1;
                const size_t o1 = ((size_t)(row + 8) * (2 * DDIM) + col) >> 1;
                ((uint32_t*)g_qkvh)[o0] = h0; ((uint32_t*)g_qkvl)[o0] = l0;
                ((uint32_t*)g_qkvh)[o1] = h1; ((uint32_t*)g_qkvl)[o1] = l1;
            }
        }
    }
}

__global__ void __launch_bounds__(256, 2) qkv_gemm_kernel() {
    gemm_mma_body<1>(g_xh, g_xl, g_wah, g_wal, g_qkv, MR, NQKV, DDIM);
}
__global__ void __launch_bounds__(256, 2) proj_gemm_kernel(float* __restrict__ out) {
    gemm_mma_body<0>(g_yh, g_yl, g_wph, g_wpl, out, MR, DDIM, DDIM);
}

// ---------------------------------------------------------------------------
// Tensor-core flash attention. Br=Bc=64, 8 warps (4m x 2n strips).
// Single-buffered K/V (proven simple ledger); smem 115712 B <= proven 119040.
// P tile overlaps the S scratch region (read-to-regs + sync before overwrite).
// ---------------------------------------------------------------------------
#define FQH 0u
#define FQL 16384u
#define FKH 32768u
#define FKL 49152u
#define FVH 65536u
#define FVL 81920u
#define FSS 98304u            // fp32 S [64][66] = 16896 B
#define FPH 98304u            // P hi bf16 64x128B (overlaps FSS after sync)
#define FPL 106496u           // P lo
#define FAL 115200u           // 64 fp32 alpha
#define FLS 115456u           // 64 fp32 l
#define SMEM_FLA 115712

__device__ __forceinline__ uint32_t fo256(int r, int cb) {
    return (uint32_t)(r * 256 + (((cb >> 4) ^ (r & 7)) << 4) + (cb & 15));
}
__device__ __forceinline__ uint32_t fo128(int r, int cb) {
    return (uint32_t)(r * 128 + ((((cb >> 4) ^ (r & 7)) & 7) << 4) + (cb & 15));
}

__global__ void __launch_bounds__(256) flash_kernel()
{
    extern __shared__ char smf[];
    const uint32_t sb = smem_u32(smf);
    float* Ss       = (float*)(smf + FSS);
    float* alpha_sm = (float*)(smf + FAL);
    float* l_sm     = (float*)(smf + FLS);

    const int tid = threadIdx.x, lane = tid & 31, w = tid >> 5;
    const int wm = w & 3, wn = w >> 2;
    const int qt = blockIdx.x, h = blockIdx.y, b = blockIdx.z;
    const int q0 = qt * 64;
    const int NIT = qt + 1;
    const size_t rowbase = (size_t)b * TT;
    const size_t vb = (size_t)(b * HH + h) * HDIM * TT;
    const int ty = tid >> 4, tx = tid & 15;

    const int a_r  = (lane & 7) + 8 * ((lane >> 3) & 1);
    const int a_cb = 16 * (lane >> 4);
    const int b_r  = (lane & 7) + 8 * (lane >> 4);
    const int b_cb = 16 * ((lane >> 3) & 1);
    const int rr = lane >> 2, cc = (lane & 3) * 2;
    const float scale = 0.088388347648318447f;   // 1/sqrt(128)

    // ---- Q hi/lo load: row stride 2*DDIM (writer layout) ----
#pragma unroll
    for (int i = 0; i < 4; i++) {
        int idx = i * 256 + tid;
        int r = idx >> 4, c = idx & 15;
        uint32_t o = fo256(r, c * 16);
        const size_t go = (rowbase + q0 + r) * (size_t)(2 * DDIM) + h * HDIM + c * 8;
        cp16(sb + FQH + o, g_qkvh + go);
        cp16(sb + FQL + o, g_qkvl + go);
    }
    cp_commit();

    float o_acc[8][4];
#pragma unroll
    for (int nf = 0; nf < 8; nf++)
#pragma unroll
        for (int q = 0; q < 4; q++) o_acc[nf][q] = 0.f;
    float m_i[4], l_i[4];
#pragma unroll
    for (int i = 0; i < 4; i++) { m_i[i] = -INFINITY; l_i[i] = 0.f; }

    for (int it = 0; it < NIT; ++it) {
        const int k0 = it * 64;
        // ---- K (stride 2*DDIM, offset DDIM) + V^T (stride TT) ----
#pragma unroll
        for (int i = 0; i < 4; i++) {
            int idx = i * 256 + tid;
            int r = idx >> 4, c = idx & 15;
            uint32_t o = fo256(r, c * 16);
            const size_t gk = (rowbase + k0 + r) * (size_t)(2 * DDIM) + DDIM + h * HDIM + c * 8;
            cp16(sb + FKH + o, g_qkvh + gk);
            cp16(sb + FKL + o, g_qkvl + gk);
        }
#pragma unroll
        for (int i = 0; i < 4; i++) {
            int idx = i * 256 + tid;
            int r = idx >> 3, c = idx & 7;
            uint32_t o = fo128(r, c * 16);
            const size_t gv = vb + (size_t)r * TT + k0 + c * 8;
            cp16(sb + FVH + o, g_vth + gv);
            cp16(sb + FVL + o, g_vtl + gv);
        }
        cp_commit();
        cp_wait0();
        __syncthreads();

        // ---- S = Q K^T (3-product hi/lo split), warp strip 16x32 ----
        {
            float s[4][4];
#pragma unroll
            for (int nf = 0; nf < 4; nf++)
#pragma unroll
                for (int q = 0; q < 4; q++) s[nf][q] = 0.f;
#pragma unroll
            for (int g = 0; g < 8; g++) {
                uint32_t qh[4], ql[4];
                ldsm4(qh, sb + FQH + fo256(wm * 16 + a_r, g * 32 + a_cb));
                ldsm4(ql, sb + FQL + fo256(wm * 16 + a_r, g * 32 + a_cb));
#pragma unroll
                for (int j = 0; j < 2; j++) {
                    uint32_t kh[4], kl[4];
                    ldsm4(kh, sb + FKH + fo256(wn * 32 + j * 16 + b_r, g * 32 + b_cb));
                    ldsm4(kl, sb + FKL + fo256(wn * 32 + j * 16 + b_r, g * 32 + b_cb));
                    mma16816(s[2 * j], qh, kh);  mma16816(s[2 * j + 1], qh, kh + 2);
                    mma16816(s[2 * j], qh, kl);  mma16816(s[2 * j + 1], qh, kl + 2);
                    mma16816(s[2 * j], ql, kh);  mma16816(s[2 * j + 1], ql, kh + 2);
                }
            }
#pragma unroll
            for (int nf = 0; nf < 4; nf++) {
                const int col = wn * 32 + nf * 8 + cc;
                *(float2*)&Ss[(wm * 16 + rr) * 66 + col]     = make_float2(s[nf][0], s[nf][1]);
                *(float2*)&Ss[(wm * 16 + rr + 8) * 66 + col] = make_float2(s[nf][2], s[nf][3]);
            }
        }
        __syncthreads();

        // ---- softmax: read ALL S values to regs, sync, then overwrite region with P ----
        float svb[4][4];
#pragma unroll
        for (int i = 0; i < 4; i++) {
            float2 u0 = *(float2*)&Ss[(4 * ty + i) * 66 + 4 * tx];
            float2 u1 = *(float2*)&Ss[(4 * ty + i) * 66 + 4 * tx + 2];
            svb[i][0] = u0.x; svb[i][1] = u0.y; svb[i][2] = u1.x; svb[i][3] = u1.y;
        }
        __syncthreads();
        {
            const bool diag = (it == qt);
#pragma unroll
            for (int i = 0; i < 4; i++) {
                float sv[4] = {svb[i][0] * scale, svb[i][1] * scale,
                               svb[i][2] * scale, svb[i][3] * scale};
                if (diag) {
#pragma unroll
                    for (int j = 0; j < 4; j++)
                        if (4 * tx + j > 4 * ty + i) sv[j] = -INFINITY;
                }
                float v = fmaxf(fmaxf(sv[0], sv[1]), fmaxf(sv[2], sv[3]));
#pragma unroll
                for (int off = 8; off; off >>= 1)
                    v = fmaxf(v, __shfl_xor_sync(0xffffffffu, v, off, 16));
                const float mnew = fmaxf(m_i[i], v);
                const float alpha = fast_exp(m_i[i] - mnew);
                m_i[i] = mnew;
                float p0 = fast_exp(sv[0] - mnew), p1 = fast_exp(sv[1] - mnew);
                float p2 = fast_exp(sv[2] - mnew), p3 = fast_exp(sv[3] - mnew);
                float rs = p0 + p1 + p2 + p3;
#pragma unroll
                for (int off = 8; off; off >>= 1)
                    rs += __shfl_xor_sync(0xffffffffu, rs, off, 16);
                l_i[i] = l_i[i] * alpha + rs;
                uint32_t wh0, wl0, wh1, wl1;
                splitpack(p0, p1, wh0, wl0);
                splitpack(p2, p3, wh1, wl1);
                const uint32_t ad = fo128(4 * ty + i, 8 * tx);
                *(uint32_t*)(smf + FPH + ad)     = wh0;
                *(uint32_t*)(smf + FPH + ad + 4) = wh1;
                *(uint32_t*)(smf + FPL + ad)     = wl0;
                *(uint32_t*)(smf + FPL + ad + 4) = wl1;
                if (tx == 0) { alpha_sm[4 * ty + i] = alpha; l_sm[4 * ty + i] = l_i[i]; }
            }
        }
        __syncthreads();

        // ---- O += P V (3-product split), V^T as K-major B operand ----
        {
            const float a0 = alpha_sm[wm * 16 + rr];
            const float a1 = alpha_sm[wm * 16 + rr + 8];
#pragma unroll
            for (int nf = 0; nf < 8; nf++) {
                o_acc[nf][0] *= a0; o_acc[nf][1] *= a0;
                o_acc[nf][2] *= a1; o_acc[nf][3] *= a1;
            }
#pragma unroll
            for (int kk = 0; kk < 4; kk++) {
                uint32_t ph[4], pl[4];
                ldsm4(ph, sb + FPH + fo128(wm * 16 + a_r, kk * 32 + a_cb));
                ldsm4(pl, sb + FPL + fo128(wm * 16 + a_r, kk * 32 + a_cb));
#pragma unroll
                for (int j = 0; j < 4; j++) {
                    uint32_t vh[4], vl[4];
                    ldsm4(vh, sb + FVH + fo128(wn * 64 + j * 16 + b_r, kk * 32 + b_cb));
                    ldsm4(vl, sb + FVL + fo128(wn * 64 + j * 16 + b_r, kk * 32 + b_cb));
                    mma16816(o_acc[2 * j], ph, vh);  mma16816(o_acc[2 * j + 1], ph, vh + 2);
                    mma16816(o_acc[2 * j], ph, vl);  mma16816(o_acc[2 * j + 1], ph, vl + 2);
                    mma16816(o_acc[2 * j], pl, vh);  mma16816(o_acc[2 * j + 1], pl, vh + 2);
                }
            }
        }
        __syncthreads();   // protect K/V/P before next iteration's loads
    }

    // ---- epilogue: y = O / l (fp32, frag layout) ----
    const float linv0 = 1.f / l_sm[wm * 16 + rr];
    const float linv1 = 1.f / l_sm[wm * 16 + rr + 8];
    const size_t r0 = (rowbase + q0 + wm * 16 + rr) * (size_t)DDIM + h * HDIM;
#pragma unroll
    for (int nf = 0; nf < 8; nf++) {
        const int col = wn * 64 + nf * 8 + cc;
        *(float2*)&g_y[r0 + col] =
            make_float2(o_acc[nf][0] * linv0, o_acc[nf][1] * linv0);
        *(float2*)&g_y[r0 + (size_t)8 * DDIM + col] =
            make_float2(o_acc[nf][2] * linv1, o_acc[nf][3] * linv1);
    }
}

// ---------------------------------------------------------------------------
extern "C" void kernel_launch(void* const* d_in, const int* in_sizes, int n_in,
                              void* d_out, int out_size)
{
    (void)in_sizes; (void)n_in; (void)out_size;
    const float* x      = (const float*)d_in[0];
    const float* w_attn = (const float*)d_in[1];
    const float* w_proj = (const float*)d_in[2];
    float* out = (float*)d_out;

    cudaFuncSetAttribute(flash_kernel,     cudaFuncAttributeMaxDynamicSharedMemorySize, SMEM_FLA);
    cudaFuncSetAttribute(qkv_gemm_kernel,  cudaFuncAttributeMaxDynamicSharedMemorySize, SMEM_MMA);
    cudaFuncSetAttribute(proj_gemm_kernel, cudaFuncAttributeMaxDynamicSharedMemorySize, SMEM_MMA);

    split_x_kernel<<<(size_t)MR * DDIM / 4 / 256, 256>>>(x);
    split_wa_kernel<<<dim3(NQKV / 32, DDIM / 32), dim3(32, 8)>>>(w_attn);
    split_wp_kernel<<<dim3(DDIM / 32, DDIM / 32), dim3(32, 8)>>>(w_proj);

    qkv_gemm_kernel<<<dim3(NQKV / 128, MR / 128), 256, SMEM_MMA>>>();

    vtrans_kernel<<<dim3(TT / 32, HDIM / 32, BB * HH), dim3(32, 8)>>>();

    flash_kernel<<<dim3(TT / 64, HH, BB), 256, SMEM_FLA>>>();

    split_y_kernel<<<(size_t)MR * DDIM / 4 / 256, 256>>>();

    proj_gemm_kernel<<<dim3(DDIM / 128, MR / 128), 256, SMEM_MMA>>>(out);
}